// round 3
// baseline (speedup 1.0000x reference)
#include <cuda_runtime.h>
#include <cuda_bf16.h>
#include <cstdint>

#define NNODES 100000
#define HD 128
#define ROW 640      // 5*HD
#define LMAX 262144

// counting-sort scratch
__device__ int   g_cnt[2 * NNODES];
__device__ int   g_off[2 * NNODES];
__device__ int   g_cur[2 * NNODES];
__device__ float g_inv[2 * NNODES];
__device__ int   g_list[2 * LMAX];

// ---------------------------------------------------------------------------
// fast cos: Cody-Waite FMA reduction + cephes minimax polys. |x|<=~1000 here.
// ---------------------------------------------------------------------------
__device__ __forceinline__ float fast_cos(float x) {
    float j = rintf(x * 0.63661977236758134f);
    int   q = (int)j;
    float r = fmaf(j, -1.5707963705062866f, x);
    r = fmaf(j, 4.3711390e-8f, r);
    float r2 = r * r;
    float ps = fmaf(r2, -1.9515295891e-4f, 8.3321608736e-3f);
    ps = fmaf(r2, ps, -1.6666654611e-1f);
    float s  = fmaf(r * r2, ps, r);
    float pc = fmaf(r2, 2.443315711809948e-5f, -1.388731625493765e-3f);
    pc = fmaf(r2, pc, 4.166664568298827e-2f);
    pc = fmaf(r2, pc, -0.5f);
    float c  = fmaf(r2, pc, 1.0f);
    float v = (q & 1) ? s : c;
    if ((q + 1) & 2) v = -v;
    return v;
}

// ---------------------------------------------------------------------------
// 1) zero the count arrays (tiny)
// ---------------------------------------------------------------------------
__global__ void k_init() {
    int i = blockIdx.x * blockDim.x + threadIdx.x;
    if (i < 2 * NNODES) g_cnt[i] = 0;
}

// ---------------------------------------------------------------------------
// 2) per-event count of src / dst occurrences
// ---------------------------------------------------------------------------
__global__ void k_count(const int* __restrict__ src, const int* __restrict__ dst,
                        int L) {
    int i = blockIdx.x * blockDim.x + threadIdx.x;
    if (i >= L) return;
    atomicAdd(&g_cnt[src[i]], 1);
    atomicAdd(&g_cnt[NNODES + dst[i]], 1);
}

// ---------------------------------------------------------------------------
// 3) exclusive scan of counts -> offsets; also zero cursors, store inv counts.
//    2 blocks (one per side), 1024 threads, chunked sequential + shared scan.
// ---------------------------------------------------------------------------
__global__ void k_scan() {
    const int base  = blockIdx.x * NNODES;
    const int chunk = (NNODES + 1023) / 1024;   // 98
    int t  = threadIdx.x;
    int s0 = t * chunk;
    int s1 = min(s0 + chunk, NNODES);
    int sum = 0;
    for (int i = s0; i < s1; i++) sum += g_cnt[base + i];
    __shared__ int sh[1024];
    sh[t] = sum;
    __syncthreads();
    for (int d = 1; d < 1024; d <<= 1) {
        int v = 0;
        if (t >= d) v = sh[t - d];
        __syncthreads();
        if (t >= d) sh[t] += v;
        __syncthreads();
    }
    int excl = (t == 0) ? 0 : sh[t - 1];
    for (int i = s0; i < s1; i++) {
        int c = g_cnt[base + i];
        g_off[base + i] = excl;
        g_cur[base + i] = 0;
        g_inv[base + i] = 1.0f / (float)max(c, 1);
        excl += c;
    }
}

// ---------------------------------------------------------------------------
// 4) fill per-node event lists via atomic cursors (counting sort)
// ---------------------------------------------------------------------------
__global__ void k_fill(const int* __restrict__ src, const int* __restrict__ dst,
                       int L) {
    int i = blockIdx.x * blockDim.x + threadIdx.x;
    if (i >= L) return;
    int s = src[i];
    int p = atomicAdd(&g_cur[s], 1);
    g_list[g_off[s] + p] = i;
    int d = dst[i];
    p = atomicAdd(&g_cur[NNODES + d], 1);
    g_list[LMAX + g_off[NNODES + d] + p] = i;
}

// ---------------------------------------------------------------------------
// 5) segmented gather: one 128-thread block per (side, node). Accumulates all
//    5 output blocks in registers over this node's events, writes the 640-wide
//    row exactly once. No atomics, no zeroing pass.
// ---------------------------------------------------------------------------
__global__ void __launch_bounds__(128)
k_gather(const int* __restrict__ type, const int* __restrict__ src,
         const float* __restrict__ sm, const int* __restrict__ dst,
         const float* __restrict__ dm, const float* __restrict__ E,
         const float* __restrict__ em, const float* __restrict__ ts,
         const float* __restrict__ mem, const float* __restrict__ lu,
         const float* __restrict__ w, const float* __restrict__ b,
         float* __restrict__ out) {
    int slot  = blockIdx.x;                // 0..2N-1 == output row index
    int h     = threadIdx.x;
    bool dside = slot >= NNODES;
    int n     = dside ? slot - NNODES : slot;

    int   off = g_off[slot];
    int   cnt = g_cnt[slot];
    float inv = g_inv[slot];
    float lun = __ldg(lu + n);
    float wv  = __ldg(w + h), bv = __ldg(b + h);
    const int* list = g_list + (dside ? LMAX : 0);

    float a0 = 0.f, a1 = 0.f, a2 = 0.f, a3 = 0.f, a4 = 0.f;
    for (int j = 0; j < cnt; j++) {
        int   e   = list[off + j];
        float smv = __ldg(sm + e), dmv = __ldg(dm + e);
        float emv = __ldg(em + e), t   = __ldg(ts + e);
        float ty  = (float)__ldg(type + e);
        int other = dside ? __ldg(src + e) : __ldg(dst + e);
        // src-side message scale = event_mask; dst-side = dst_mask
        float cb = dside ? dmv : emv;
        float cm = dside ? smv * dmv : dmv * emv;   // coeff on mem[other]
        float c1 = dside ? dmv * dmv : smv * emv;   // coeff on mem[n] (block1)
        // faithful to reference: both sides use lu * dst_mask
        float x  = t - lun * dmv;
        a0 += ty * cb;
        a1 += c1;
        a2 += __ldg(mem + (size_t)other * HD + h) * cm;
        a3 += fast_cos(fmaf(x, wv, bv)) * cb;
        a4 += __ldg(E + (size_t)e * HD + h) * cb;
    }
    float mv = __ldg(mem + (size_t)n * HD + h);
    float* o = out + (size_t)slot * ROW;
    o[h]       = a0 * inv;
    o[128 + h] = mv * (a1 * inv);
    o[256 + h] = a2 * inv;
    o[384 + h] = a3 * inv;
    o[512 + h] = a4 * inv;
}

// ---------------------------------------------------------------------------
extern "C" void kernel_launch(void* const* d_in, const int* in_sizes, int n_in,
                              void* d_out, int out_size) {
    const int*   type = (const int*)  d_in[0];
    const int*   src  = (const int*)  d_in[1];
    const float* smk  = (const float*)d_in[2];
    const int*   dst  = (const int*)  d_in[3];
    const float* dmk  = (const float*)d_in[4];
    const float* E    = (const float*)d_in[5];
    const float* em   = (const float*)d_in[6];
    const float* ts   = (const float*)d_in[7];
    const float* mem  = (const float*)d_in[8];
    const float* lu   = (const float*)d_in[9];
    const float* w    = (const float*)d_in[10];
    const float* b    = (const float*)d_in[11];
    float* out = (float*)d_out;
    int L = in_sizes[0];
    if (L > LMAX) L = LMAX;

    k_init <<<(2 * NNODES + 255) / 256, 256>>>();
    k_count<<<(L + 255) / 256, 256>>>(src, dst, L);
    k_scan <<<2, 1024>>>();
    k_fill <<<(L + 255) / 256, 256>>>(src, dst, L);
    k_gather<<<2 * NNODES, 128>>>(type, src, smk, dst, dmk, E, em, ts, mem, lu,
                                  w, b, out);
}

// round 4
// speedup vs baseline: 1.3019x; 1.3019x over previous
#include <cuda_runtime.h>
#include <cuda_bf16.h>
#include <cstdint>

#define NNODES 100000
#define HD 128
#define ROW 640      // 5*HD
#define LMAX 262144

// scratch
__device__ int    g_cnt[2 * NNODES];
__device__ int    g_off[2 * NNODES];
__device__ int    g_cur[2 * NNODES];
__device__ float  g_inv[2 * NNODES];
// sorted per-(side,position) event records: 2 float4s each.
// rec[2*(side*LMAX+p)+0] = {bits(e), bits(other), s0, c1}
// rec[2*(side*LMAX+p)+1] = {cm, cb, x, unused}
__device__ float4 g_rec[4 * LMAX];

// ---------------------------------------------------------------------------
// fast cos: Cody-Waite FMA reduction + cephes minimax polys. |x|<=~1000 here.
// ---------------------------------------------------------------------------
__device__ __forceinline__ float fast_cos(float x) {
    float j = rintf(x * 0.63661977236758134f);
    int   q = (int)j;
    float r = fmaf(j, -1.5707963705062866f, x);
    r = fmaf(j, 4.3711390e-8f, r);
    float r2 = r * r;
    float ps = fmaf(r2, -1.9515295891e-4f, 8.3321608736e-3f);
    ps = fmaf(r2, ps, -1.6666654611e-1f);
    float s  = fmaf(r * r2, ps, r);
    float pc = fmaf(r2, 2.443315711809948e-5f, -1.388731625493765e-3f);
    pc = fmaf(r2, pc, 4.166664568298827e-2f);
    pc = fmaf(r2, pc, -0.5f);
    float c  = fmaf(r2, pc, 1.0f);
    float v = (q & 1) ? s : c;
    if ((q + 1) & 2) v = -v;
    return v;
}

// ---------------------------------------------------------------------------
__global__ void k_init() {
    int i = blockIdx.x * blockDim.x + threadIdx.x;
    if (i < 2 * NNODES) g_cnt[i] = 0;
}

__global__ void k_count(const int* __restrict__ src, const int* __restrict__ dst,
                        int L) {
    int i = blockIdx.x * blockDim.x + threadIdx.x;
    if (i >= L) return;
    atomicAdd(&g_cnt[src[i]], 1);
    atomicAdd(&g_cnt[NNODES + dst[i]], 1);
}

// exclusive scan of counts -> offsets; zero cursors; inverse counts.
__global__ void k_scan() {
    const int base  = blockIdx.x * NNODES;
    const int chunk = (NNODES + 1023) / 1024;
    int t  = threadIdx.x;
    int s0 = t * chunk;
    int s1 = min(s0 + chunk, NNODES);
    int sum = 0;
    for (int i = s0; i < s1; i++) sum += g_cnt[base + i];
    __shared__ int sh[1024];
    sh[t] = sum;
    __syncthreads();
    for (int d = 1; d < 1024; d <<= 1) {
        int v = 0;
        if (t >= d) v = sh[t - d];
        __syncthreads();
        if (t >= d) sh[t] += v;
        __syncthreads();
    }
    int excl = (t == 0) ? 0 : sh[t - 1];
    for (int i = s0; i < s1; i++) {
        int c = g_cnt[base + i];
        g_off[base + i] = excl;
        g_cur[base + i] = 0;
        g_inv[base + i] = 1.0f / (float)max(c, 1);
        excl += c;
    }
}

// counting-sort fill: write fully-precomputed records at sorted positions.
__global__ void k_fill(const int* __restrict__ type, const int* __restrict__ src,
                       const float* __restrict__ sm, const int* __restrict__ dst,
                       const float* __restrict__ dm, const float* __restrict__ em,
                       const float* __restrict__ ts, const float* __restrict__ lu,
                       int L) {
    int i = blockIdx.x * blockDim.x + threadIdx.x;
    if (i >= L) return;
    int   s   = src[i], d = dst[i];
    float smv = sm[i], dmv = dm[i], emv = em[i], t = ts[i];
    float ty  = (float)type[i];
    float lus = __ldg(lu + s), lud = __ldg(lu + d);

    // src side: message scale cb = event_mask
    int p = atomicAdd(&g_cur[s], 1) + g_off[s];
    g_rec[2 * p]     = make_float4(__int_as_float(i), __int_as_float(d),
                                   ty * emv, smv * emv);
    g_rec[2 * p + 1] = make_float4(dmv * emv, emv, t - lus * dmv, 0.0f);

    // dst side: message scale cb = dst_mask (faithful: lu*dst_mask both sides)
    p = atomicAdd(&g_cur[NNODES + d], 1) + g_off[NNODES + d] + LMAX;
    g_rec[2 * p]     = make_float4(__int_as_float(i), __int_as_float(s),
                                   ty * dmv, dmv * dmv);
    g_rec[2 * p + 1] = make_float4(smv * dmv, dmv, t - lud * dmv, 0.0f);
}

// ---------------------------------------------------------------------------
// gather: one warp per (side,node), lane l owns h = 4l..4l+3 (float4 rows).
// Software-pipelined over the node's sorted records; row written exactly once.
// ---------------------------------------------------------------------------
__global__ void __launch_bounds__(256)
k_gather(const float4* __restrict__ E4, const float4* __restrict__ M4,
         const float4* __restrict__ W4, const float4* __restrict__ B4,
         float4* __restrict__ out4) {
    int gw   = (blockIdx.x * blockDim.x + threadIdx.x) >> 5;
    int lane = threadIdx.x & 31;
    if (gw >= 2 * NNODES) return;
    int  slot  = gw;
    bool dside = slot >= NNODES;
    int  n     = dside ? slot - NNODES : slot;

    int   off = g_off[slot] + (dside ? LMAX : 0);
    int   cnt = g_cnt[slot];
    float inv = g_inv[slot];
    float4 wv = __ldg(W4 + lane), bv = __ldg(B4 + lane);

    float  a0 = 0.f, a1 = 0.f;
    float4 a2 = make_float4(0, 0, 0, 0);
    float4 a3 = make_float4(0, 0, 0, 0);
    float4 a4 = make_float4(0, 0, 0, 0);

    float4 ra, rb;
    if (cnt > 0) { ra = __ldg(g_rec + 2 * off); rb = __ldg(g_rec + 2 * off + 1); }
    for (int j = 0; j < cnt; j++) {
        // prefetch next record while this iteration's gathers are in flight
        float4 ra_n, rb_n;
        if (j + 1 < cnt) {
            ra_n = __ldg(g_rec + 2 * (off + j + 1));
            rb_n = __ldg(g_rec + 2 * (off + j + 1) + 1);
        }
        int   e     = __float_as_int(ra.x);
        int   other = __float_as_int(ra.y);
        float cm = rb.x, cb = rb.y, x = rb.z;
        float4 Ev = __ldg(E4 + (size_t)e * 32 + lane);
        float4 Mv = __ldg(M4 + (size_t)other * 32 + lane);
        a0 += ra.z;
        a1 += ra.w;
        a2.x = fmaf(Mv.x, cm, a2.x); a2.y = fmaf(Mv.y, cm, a2.y);
        a2.z = fmaf(Mv.z, cm, a2.z); a2.w = fmaf(Mv.w, cm, a2.w);
        a3.x = fmaf(fast_cos(fmaf(x, wv.x, bv.x)), cb, a3.x);
        a3.y = fmaf(fast_cos(fmaf(x, wv.y, bv.y)), cb, a3.y);
        a3.z = fmaf(fast_cos(fmaf(x, wv.z, bv.z)), cb, a3.z);
        a3.w = fmaf(fast_cos(fmaf(x, wv.w, bv.w)), cb, a3.w);
        a4.x = fmaf(Ev.x, cb, a4.x); a4.y = fmaf(Ev.y, cb, a4.y);
        a4.z = fmaf(Ev.z, cb, a4.z); a4.w = fmaf(Ev.w, cb, a4.w);
        ra = ra_n; rb = rb_n;
    }

    float4 Mn = __ldg(M4 + (size_t)n * 32 + lane);
    float  b0 = a0 * inv, b1 = a1 * inv;
    float4* o = out4 + (size_t)slot * 160;   // 640/4
    o[lane]       = make_float4(b0, b0, b0, b0);
    o[32 + lane]  = make_float4(Mn.x * b1, Mn.y * b1, Mn.z * b1, Mn.w * b1);
    o[64 + lane]  = make_float4(a2.x * inv, a2.y * inv, a2.z * inv, a2.w * inv);
    o[96 + lane]  = make_float4(a3.x * inv, a3.y * inv, a3.z * inv, a3.w * inv);
    o[128 + lane] = make_float4(a4.x * inv, a4.y * inv, a4.z * inv, a4.w * inv);
}

// ---------------------------------------------------------------------------
extern "C" void kernel_launch(void* const* d_in, const int* in_sizes, int n_in,
                              void* d_out, int out_size) {
    const int*   type = (const int*)  d_in[0];
    const int*   src  = (const int*)  d_in[1];
    const float* smk  = (const float*)d_in[2];
    const int*   dst  = (const int*)  d_in[3];
    const float* dmk  = (const float*)d_in[4];
    const float* E    = (const float*)d_in[5];
    const float* em   = (const float*)d_in[6];
    const float* ts   = (const float*)d_in[7];
    const float* mem  = (const float*)d_in[8];
    const float* lu   = (const float*)d_in[9];
    const float* w    = (const float*)d_in[10];
    const float* b    = (const float*)d_in[11];
    float* out = (float*)d_out;
    int L = in_sizes[0];
    if (L > LMAX) L = LMAX;

    k_init <<<(2 * NNODES + 255) / 256, 256>>>();
    k_count<<<(L + 255) / 256, 256>>>(src, dst, L);
    k_scan <<<2, 1024>>>();
    k_fill <<<(L + 255) / 256, 256>>>(type, src, smk, dst, dmk, em, ts, lu, L);

    int warps = 2 * NNODES;
    k_gather<<<(warps * 32 + 255) / 256, 256>>>(
        (const float4*)E, (const float4*)mem, (const float4*)w,
        (const float4*)b, (float4*)out);
}